// round 1
// baseline (speedup 1.0000x reference)
#include <cuda_runtime.h>
#include <math.h>

#define ED 768
#define NH 12
#define HD 64
#define NBATCH 16
#define SEQ 1024
#define MTOT (NBATCH * SEQ)   // 16384

// Scratch (allocation-free rule: __device__ globals)
__device__ float g_q[(size_t)NBATCH * NH * SEQ * HD];     // [B,H,S,D], pre-scaled by 1/sqrt(D)
__device__ float g_k[(size_t)NBATCH * NH * SEQ * HD];     // [B,H,S,D]
__device__ float g_v[(size_t)NBATCH * NH * SEQ * HD];     // [B,H,S,D]
__device__ float g_attn[(size_t)MTOT * ED];               // [B*S, E]

// ---------------------------------------------------------------------------
// 128x128x16 register-tiled SGEMM, 256 threads, 8x8 micro-tile per thread.
// MODE 0: C = x @ qkv_w + qkv_b, scattered into g_q/g_k/g_v ([B,H,S,D]),
//         Q part scaled by 0.125.
// MODE 1: C = g_attn @ proj_w + proj_b -> out ([B*S, E])
// ---------------------------------------------------------------------------
template <int MODE>
__global__ __launch_bounds__(256)
void sgemm_kernel(const float* __restrict__ Ain,
                  const float* __restrict__ W,
                  const float* __restrict__ bias,
                  float* __restrict__ C, int N)
{
    __shared__ float As[16][128];   // transposed: As[k][m]
    __shared__ float Bs[16][128];   // Bs[k][n]

    const float* A = (MODE == 1) ? g_attn : Ain;

    const int tid = threadIdx.x;
    const int ty = tid >> 4;        // 0..15
    const int tx = tid & 15;        // 0..15
    const int rowBase = blockIdx.y * 128;
    const int colBase = blockIdx.x * 128;

    float acc[8][8];
#pragma unroll
    for (int i = 0; i < 8; i++)
#pragma unroll
        for (int j = 0; j < 8; j++) acc[i][j] = 0.f;

    for (int k0 = 0; k0 < 768; k0 += 16) {
        // Load A tile 128x16 (transposed into smem)
#pragma unroll
        for (int u = 0; u < 2; u++) {
            int f = tid + u * 256;              // 0..511
            int r = f >> 2;                     // 0..127
            int c = (f & 3) << 2;               // 0,4,8,12
            float4 va = *(const float4*)(A + (size_t)(rowBase + r) * 768 + k0 + c);
            As[c + 0][r] = va.x;
            As[c + 1][r] = va.y;
            As[c + 2][r] = va.z;
            As[c + 3][r] = va.w;
        }
        // Load B tile 16x128
#pragma unroll
        for (int u = 0; u < 2; u++) {
            int f = tid + u * 256;              // 0..511
            int kr = f >> 5;                    // 0..15
            int c = (f & 31) << 2;              // 0..124
            *(float4*)&Bs[kr][c] = *(const float4*)(W + (size_t)(k0 + kr) * N + colBase + c);
        }
        __syncthreads();

#pragma unroll
        for (int k = 0; k < 16; k++) {
            float a[8], b[8];
            *(float4*)&a[0] = *(const float4*)&As[k][ty * 8];
            *(float4*)&a[4] = *(const float4*)&As[k][ty * 8 + 4];
            *(float4*)&b[0] = *(const float4*)&Bs[k][tx * 8];
            *(float4*)&b[4] = *(const float4*)&Bs[k][tx * 8 + 4];
#pragma unroll
            for (int i = 0; i < 8; i++)
#pragma unroll
                for (int j = 0; j < 8; j++)
                    acc[i][j] = fmaf(a[i], b[j], acc[i][j]);
        }
        __syncthreads();
    }

    // Epilogue
#pragma unroll
    for (int i = 0; i < 8; i++) {
        int row = rowBase + ty * 8 + i;
#pragma unroll
        for (int j = 0; j < 8; j++) {
            int col = colBase + tx * 8 + j;
            float v = acc[i][j] + bias[col];
            if (MODE == 0) {
                int part = col / ED;            // 0=Q 1=K 2=V
                int e = col - part * ED;
                int h = e >> 6;
                int d = e & 63;
                int b = row >> 10;
                int s = row & 1023;
                if (part == 0) v *= 0.125f;     // fold 1/sqrt(64) into Q
                float* dst = (part == 0) ? g_q : (part == 1) ? g_k : g_v;
                dst[((size_t)(b * NH + h) * SEQ + s) * HD + d] = v;
            } else {
                C[(size_t)row * ED + col] = v;
            }
        }
    }
}

// ---------------------------------------------------------------------------
// Flash attention, fp32. One block = one (b,h) x 64-row Q tile.
// 256 threads (16x16), each owns a 4x4 micro-tile of the 64x64 score tile.
// smem: Qs[64][65], Kt[64][65] (K transposed: Kt[d][kc]), Vs[64][65], Ps[64][65]
// All smem read patterns are bank-conflict-free with the 65-float pitch.
// ---------------------------------------------------------------------------
#define ATTN_SMEM_FLOATS (4 * 64 * 65)
#define ATTN_SMEM_BYTES (ATTN_SMEM_FLOATS * 4)

__global__ __launch_bounds__(256)
void attn_kernel()
{
    extern __shared__ float sm[];
    float* Qs = sm;                      // [64][65]
    float* Kt = sm + 64 * 65;            // [64][65], Kt[d*65 + kc]
    float* Vs = sm + 2 * 64 * 65;        // [64][65]
    float* Ps = sm + 3 * 64 * 65;        // [64][65]

    const int tid = threadIdx.x;
    const int ty = tid >> 4;             // 0..15
    const int tx = tid & 15;             // 0..15
    const int qt = blockIdx.x;           // 0..15 (q tile)
    const int bh = blockIdx.y;           // 0..191 (b*NH + h)

    const float* Qg = g_q + (size_t)bh * SEQ * HD;
    const float* Kg = g_k + (size_t)bh * SEQ * HD;
    const float* Vg = g_v + (size_t)bh * SEQ * HD;

    // Load Q tile (64x64)
#pragma unroll
    for (int u = 0; u < 4; u++) {
        int f = tid + u * 256;           // 0..1023
        int r = f >> 4;                  // 0..63
        int c = (f & 15) << 2;           // 0..60
        float4 v = *(const float4*)(Qg + (size_t)(qt * 64 + r) * HD + c);
        Qs[r * 65 + c + 0] = v.x;
        Qs[r * 65 + c + 1] = v.y;
        Qs[r * 65 + c + 2] = v.z;
        Qs[r * 65 + c + 3] = v.w;
    }

    float m_i[4], l_i[4], o[4][4];
#pragma unroll
    for (int i = 0; i < 4; i++) {
        m_i[i] = -1e30f;
        l_i[i] = 0.f;
#pragma unroll
        for (int j = 0; j < 4; j++) o[i][j] = 0.f;
    }

    for (int kt = 0; kt < 16; kt++) {
        __syncthreads();   // previous iteration's reads of Kt/Vs/Ps done; also first Q-load fence

        // Load K tile transposed + V tile
#pragma unroll
        for (int u = 0; u < 4; u++) {
            int f = tid + u * 256;
            int r = f >> 4;
            int c = (f & 15) << 2;
            float4 kv = *(const float4*)(Kg + (size_t)(kt * 64 + r) * HD + c);
            Kt[(c + 0) * 65 + r] = kv.x;
            Kt[(c + 1) * 65 + r] = kv.y;
            Kt[(c + 2) * 65 + r] = kv.z;
            Kt[(c + 3) * 65 + r] = kv.w;
            float4 vv = *(const float4*)(Vg + (size_t)(kt * 64 + r) * HD + c);
            Vs[r * 65 + c + 0] = vv.x;
            Vs[r * 65 + c + 1] = vv.y;
            Vs[r * 65 + c + 2] = vv.z;
            Vs[r * 65 + c + 3] = vv.w;
        }
        __syncthreads();

        // S = Q K^T (Q already scaled)
        float s[4][4];
#pragma unroll
        for (int i = 0; i < 4; i++)
#pragma unroll
            for (int j = 0; j < 4; j++) s[i][j] = 0.f;

#pragma unroll 16
        for (int d = 0; d < 64; d++) {
            float qa[4], kb[4];
#pragma unroll
            for (int i = 0; i < 4; i++) qa[i] = Qs[(ty * 4 + i) * 65 + d];
#pragma unroll
            for (int j = 0; j < 4; j++) kb[j] = Kt[d * 65 + tx * 4 + j];
#pragma unroll
            for (int i = 0; i < 4; i++)
#pragma unroll
                for (int j = 0; j < 4; j++)
                    s[i][j] = fmaf(qa[i], kb[j], s[i][j]);
        }

        // Online softmax (row groups = 16 lanes with same ty; xor-shuffle <= 8
        // stays within the 16-lane segment)
#pragma unroll
        for (int i = 0; i < 4; i++) {
            float mx = fmaxf(fmaxf(s[i][0], s[i][1]), fmaxf(s[i][2], s[i][3]));
#pragma unroll
            for (int off = 8; off >= 1; off >>= 1)
                mx = fmaxf(mx, __shfl_xor_sync(0xffffffffu, mx, off));
            float mnew = fmaxf(m_i[i], mx);
            float corr = __expf(m_i[i] - mnew);
            float rs = 0.f;
#pragma unroll
            for (int j = 0; j < 4; j++) {
                float p = __expf(s[i][j] - mnew);
                s[i][j] = p;
                rs += p;
            }
#pragma unroll
            for (int off = 8; off >= 1; off >>= 1)
                rs += __shfl_xor_sync(0xffffffffu, rs, off);
            m_i[i] = mnew;
            l_i[i] = l_i[i] * corr + rs;
#pragma unroll
            for (int j = 0; j < 4; j++) {
                o[i][j] *= corr;
                Ps[(ty * 4 + i) * 65 + tx * 4 + j] = s[i][j];
            }
        }
        __syncthreads();

        // O += P @ V
#pragma unroll 16
        for (int c = 0; c < 64; c++) {
            float pa[4], vb[4];
#pragma unroll
            for (int i = 0; i < 4; i++) pa[i] = Ps[(ty * 4 + i) * 65 + c];
#pragma unroll
            for (int j = 0; j < 4; j++) vb[j] = Vs[c * 65 + tx * 4 + j];
#pragma unroll
            for (int i = 0; i < 4; i++)
#pragma unroll
                for (int j = 0; j < 4; j++)
                    o[i][j] = fmaf(pa[i], vb[j], o[i][j]);
        }
    }

    // Write O / l into g_attn [B*S, E] at column h*64
    const int b = bh / NH;
    const int h = bh - b * NH;
#pragma unroll
    for (int i = 0; i < 4; i++) {
        float inv = 1.0f / l_i[i];
        int srow = qt * 64 + ty * 4 + i;
        float* dst = g_attn + ((size_t)(b * SEQ + srow)) * ED + h * HD + tx * 4;
#pragma unroll
        for (int j = 0; j < 4; j++) dst[j] = o[i][j] * inv;
    }
}

// ---------------------------------------------------------------------------
// Launch
// ---------------------------------------------------------------------------
extern "C" void kernel_launch(void* const* d_in, const int* in_sizes, int n_in,
                              void* d_out, int out_size)
{
    const float* x      = (const float*)d_in[0];  // [16,1024,768]
    const float* qkv_w  = (const float*)d_in[1];  // [768,2304]
    const float* qkv_b  = (const float*)d_in[2];  // [2304]
    const float* proj_w = (const float*)d_in[3];  // [768,768]
    const float* proj_b = (const float*)d_in[4];  // [768]
    float* out = (float*)d_out;                   // [16,1024,768]

    cudaFuncSetAttribute(attn_kernel,
                         cudaFuncAttributeMaxDynamicSharedMemorySize,
                         ATTN_SMEM_BYTES);

    dim3 blk(256);
    // QKV: [16384,768] @ [768,2304] -> scatter into g_q/g_k/g_v
    sgemm_kernel<0><<<dim3((3 * ED) / 128, MTOT / 128), blk>>>(x, qkv_w, qkv_b, nullptr, 3 * ED);
    // Attention -> g_attn
    attn_kernel<<<dim3(SEQ / 64, NBATCH * NH), blk, ATTN_SMEM_BYTES>>>();
    // Projection: g_attn @ [768,768] -> out
    sgemm_kernel<1><<<dim3(ED / 128, MTOT / 128), blk>>>(nullptr, proj_w, proj_b, out, ED);
}

// round 16
// speedup vs baseline: 1.3763x; 1.3763x over previous
#include <cuda_runtime.h>
#include <cuda_bf16.h>
#include <mma.h>
#include <cstdint>
#include <math.h>

using namespace nvcuda;

#define ED 768
#define NH 12
#define HD 64
#define NBATCH 16
#define SEQ 1024
#define MTOT (NBATCH * SEQ)   // 16384

// ---------------------------------------------------------------------------
// Device-global scratch (allocation-free rule)
// ---------------------------------------------------------------------------
__device__ float g_q[(size_t)NBATCH * NH * SEQ * HD];   // [B,H,S,D], Q pre-scaled
__device__ float g_k[(size_t)NBATCH * NH * SEQ * HD];
__device__ float g_v[(size_t)NBATCH * NH * SEQ * HD];
__device__ float g_attn[(size_t)MTOT * ED];             // [B*S, E] fp32 (R1 layout)

// ---------------------------------------------------------------------------
// WMMA bf16x3-split GEMM, fp32 in / fp32 out, inline hi/lo conversion.
// C[M,N] = A[M,768] @ W[768,N] + bias.  A row-major [M][768], W row-major [768][N]
// (native harness layouts — the exact global access patterns R1 validated).
// 128x128x32 CTA tile, 8 warps (2x4), warp tile 64x32 (4x2 wmma frags).
// A staged [128m][32k] pitch 40 (row_major matrix_a);
// B staged [32k][128n] pitch 136 (row_major matrix_b) — NO transpose anywhere.
// Split trick: D = Ah*Bh + Ah*Bl + Al*Bh, fp32 accum (~1.5e-5 err).
// MODE 0: A=x, W=qkv_w (N=2304) -> scatter to g_q(*0.125)/g_k/g_v
// MODE 1: A=g_attn, W=proj_w (N=768) -> out + proj_b
// ---------------------------------------------------------------------------
#define PWA 40
#define PWB 136
#define A_TILE (128 * PWA)                    // 5120 bf16
#define B_TILE (32 * PWB)                     // 4352 bf16
#define STAGE_ELEMS (2 * A_TILE + 2 * B_TILE) // 18944 bf16
#define GEMM_SMEM_BYTES (2 * STAGE_ELEMS * 2) // 75776 B (epilogue reuses 64KB as f32 C)

__device__ __forceinline__ void cvt_store4(__nv_bfloat16* hp, __nv_bfloat16* lp, float4 v) {
    __nv_bfloat16 h0 = __float2bfloat16(v.x), h1 = __float2bfloat16(v.y);
    __nv_bfloat16 h2 = __float2bfloat16(v.z), h3 = __float2bfloat16(v.w);
    __nv_bfloat16 l0 = __float2bfloat16(v.x - __bfloat162float(h0));
    __nv_bfloat16 l1 = __float2bfloat16(v.y - __bfloat162float(h1));
    __nv_bfloat16 l2 = __float2bfloat16(v.z - __bfloat162float(h2));
    __nv_bfloat16 l3 = __float2bfloat16(v.w - __bfloat162float(h3));
    *(__nv_bfloat162*)(hp + 0) = __halves2bfloat162(h0, h1);
    *(__nv_bfloat162*)(hp + 2) = __halves2bfloat162(h2, h3);
    *(__nv_bfloat162*)(lp + 0) = __halves2bfloat162(l0, l1);
    *(__nv_bfloat162*)(lp + 2) = __halves2bfloat162(l2, l3);
}

template <int MODE>
__global__ __launch_bounds__(256)
void gemm_wmma(const float* __restrict__ Ain, const float* __restrict__ W,
               const float* __restrict__ bias, float* __restrict__ Cout, int N) {
    constexpr int KTOT = 768, BK = 32, NCHUNK = KTOT / BK;  // 24

    const float* A = (MODE == 1) ? g_attn : Ain;

    extern __shared__ char smem[];
    __nv_bfloat16* sm = (__nv_bfloat16*)smem;

    const int tid = threadIdx.x;
    const int wid = tid >> 5;
    const int warp_m = wid >> 2, warp_n = wid & 3;   // 2 x 4 warp grid
    const int rowBase = blockIdx.y * 128;
    const int colBase = blockIdx.x * 128;

    wmma::fragment<wmma::accumulator, 16, 16, 16, float> acc[4][2];
#pragma unroll
    for (int i = 0; i < 4; i++)
#pragma unroll
        for (int j = 0; j < 2; j++) wmma::fill_fragment(acc[i][j], 0.0f);

    float4 ra[4], rbv[4];
    auto gload = [&](int kc) {
        const int k0 = kc * BK;
#pragma unroll
        for (int u = 0; u < 4; u++) {
            int idx = tid + u * 256;                 // 0..1023
            int r = idx >> 3, sga = idx & 7;         // A: 128 rows x 8 segs of 4 floats
            ra[u] = *(const float4*)(A + (size_t)(rowBase + r) * KTOT + k0 + sga * 4);
            int kr = idx >> 5, sgb = idx & 31;       // B: 32 k-rows x 32 segs of 4 floats
            rbv[u] = *(const float4*)(W + (size_t)(k0 + kr) * N + colBase + sgb * 4);
        }
    };
    auto sstore = [&](int s) {
        __nv_bfloat16* base = sm + s * STAGE_ELEMS;
#pragma unroll
        for (int u = 0; u < 4; u++) {
            int idx = tid + u * 256;
            int r = idx >> 3, sga = idx & 7;
            int offA = r * PWA + sga * 4;
            cvt_store4(base + offA, base + A_TILE + offA, ra[u]);
            int kr = idx >> 5, sgb = idx & 31;
            int offB = kr * PWB + sgb * 4;
            cvt_store4(base + 2 * A_TILE + offB, base + 2 * A_TILE + B_TILE + offB, rbv[u]);
        }
    };

    gload(0);

    for (int kc = 0; kc < NCHUNK; kc++) {
        const int s = kc & 1;
        sstore(s);
        __syncthreads();
        if (kc + 1 < NCHUNK) gload(kc + 1);   // LDG latency hidden behind MMA

        const __nv_bfloat16* A_h = sm + s * STAGE_ELEMS;
        const __nv_bfloat16* B_h = A_h + 2 * A_TILE;

#pragma unroll
        for (int ks = 0; ks < 2; ks++) {
            wmma::fragment<wmma::matrix_b, 16, 16, 16, __nv_bfloat16, wmma::row_major> bh[2], bl[2];
#pragma unroll
            for (int nf = 0; nf < 2; nf++) {
                const __nv_bfloat16* bp = B_h + (ks * 16) * PWB + warp_n * 32 + nf * 16;
                wmma::load_matrix_sync(bh[nf], bp, PWB);
                wmma::load_matrix_sync(bl[nf], bp + B_TILE, PWB);
            }
#pragma unroll
            for (int mf = 0; mf < 4; mf++) {
                wmma::fragment<wmma::matrix_a, 16, 16, 16, __nv_bfloat16, wmma::row_major> ah, al;
                const __nv_bfloat16* ap = A_h + (warp_m * 64 + mf * 16) * PWA + ks * 16;
                wmma::load_matrix_sync(ah, ap, PWA);
                wmma::load_matrix_sync(al, ap + A_TILE, PWA);
#pragma unroll
                for (int nf = 0; nf < 2; nf++) {
                    wmma::mma_sync(acc[mf][nf], ah, bh[nf], acc[mf][nf]);
                    wmma::mma_sync(acc[mf][nf], ah, bl[nf], acc[mf][nf]);
                    wmma::mma_sync(acc[mf][nf], al, bh[nf], acc[mf][nf]);
                }
            }
        }
        __syncthreads();
    }

    // Epilogue: stage C tile in smem as f32 (64KB fits in 74KB), then scatter
    // with the R1-validated index formulas.
    float* cs = (float*)smem;
#pragma unroll
    for (int mf = 0; mf < 4; mf++)
#pragma unroll
        for (int nf = 0; nf < 2; nf++)
            wmma::store_matrix_sync(cs + (warp_m * 64 + mf * 16) * 128 + warp_n * 32 + nf * 16,
                                    acc[mf][nf], 128, wmma::mem_row_major);
    __syncthreads();

#pragma unroll 4
    for (int i = 0; i < 64; i++) {
        int idx = tid + i * 256;              // 0..16383
        int r = idx >> 7, c = idx & 127;
        float v = cs[r * 128 + c];
        int col = colBase + c;
        int m = rowBase + r;
        if (MODE == 0) {
            int part = col / ED;
            int e = col - part * ED;
            int h = e >> 6, d = e & 63;
            int b = m >> 10, ssq = m & 1023;
            float sc = (part == 0) ? 0.125f : 1.0f;
            float* dstp = (part == 0) ? g_q : (part == 1) ? g_k : g_v;
            dstp[((size_t)(b * NH + h) * SEQ + ssq) * HD + d] = (v + bias[col]) * sc;
        } else {
            Cout[(size_t)m * ED + col] = v + bias[col];
        }
    }
}

// ---------------------------------------------------------------------------
// Flash attention, fp32 — byte-exact round-1-validated kernel (fp32 g_attn out)
// ---------------------------------------------------------------------------
#define ATTN_SMEM_BYTES (4 * 64 * 65 * 4)

__global__ __launch_bounds__(256)
void attn_kernel() {
    extern __shared__ float smf[];
    float* Qs = smf;
    float* Kt = smf + 64 * 65;
    float* Vs = smf + 2 * 64 * 65;
    float* Ps = smf + 3 * 64 * 65;

    const int tid = threadIdx.x;
    const int ty = tid >> 4, tx = tid & 15;
    const int qt = blockIdx.x;
    const int bh = blockIdx.y;

    const float* Qg = g_q + (size_t)bh * SEQ * HD;
    const float* Kg = g_k + (size_t)bh * SEQ * HD;
    const float* Vg = g_v + (size_t)bh * SEQ * HD;

#pragma unroll
    for (int u = 0; u < 4; u++) {
        int f = tid + u * 256;
        int r = f >> 4, c = (f & 15) << 2;
        float4 v = *(const float4*)(Qg + (size_t)(qt * 64 + r) * HD + c);
        Qs[r * 65 + c + 0] = v.x; Qs[r * 65 + c + 1] = v.y;
        Qs[r * 65 + c + 2] = v.z; Qs[r * 65 + c + 3] = v.w;
    }

    float m_i[4], l_i[4], o[4][4];
#pragma unroll
    for (int i = 0; i < 4; i++) {
        m_i[i] = -1e30f; l_i[i] = 0.f;
#pragma unroll
        for (int j = 0; j < 4; j++) o[i][j] = 0.f;
    }

    for (int kt = 0; kt < 16; kt++) {
        __syncthreads();
#pragma unroll
        for (int u = 0; u < 4; u++) {
            int f = tid + u * 256;
            int r = f >> 4, c = (f & 15) << 2;
            float4 kv = *(const float4*)(Kg + (size_t)(kt * 64 + r) * HD + c);
            Kt[(c + 0) * 65 + r] = kv.x; Kt[(c + 1) * 65 + r] = kv.y;
            Kt[(c + 2) * 65 + r] = kv.z; Kt[(c + 3) * 65 + r] = kv.w;
            float4 vv = *(const float4*)(Vg + (size_t)(kt * 64 + r) * HD + c);
            Vs[r * 65 + c + 0] = vv.x; Vs[r * 65 + c + 1] = vv.y;
            Vs[r * 65 + c + 2] = vv.z; Vs[r * 65 + c + 3] = vv.w;
        }
        __syncthreads();

        float s[4][4];
#pragma unroll
        for (int i = 0; i < 4; i++)
#pragma unroll
            for (int j = 0; j < 4; j++) s[i][j] = 0.f;

#pragma unroll 16
        for (int dd = 0; dd < 64; dd++) {
            float qa[4], kb[4];
#pragma unroll
            for (int i = 0; i < 4; i++) qa[i] = Qs[(ty * 4 + i) * 65 + dd];
#pragma unroll
            for (int j = 0; j < 4; j++) kb[j] = Kt[dd * 65 + tx * 4 + j];
#pragma unroll
            for (int i = 0; i < 4; i++)
#pragma unroll
                for (int j = 0; j < 4; j++)
                    s[i][j] = fmaf(qa[i], kb[j], s[i][j]);
        }

#pragma unroll
        for (int i = 0; i < 4; i++) {
            float mx = fmaxf(fmaxf(s[i][0], s[i][1]), fmaxf(s[i][2], s[i][3]));
#pragma unroll
            for (int off = 8; off >= 1; off >>= 1)
                mx = fmaxf(mx, __shfl_xor_sync(0xffffffffu, mx, off));
            float mnew = fmaxf(m_i[i], mx);
            float corr = __expf(m_i[i] - mnew);
            float rs = 0.f;
#pragma unroll
            for (int j = 0; j < 4; j++) {
                float p = __expf(s[i][j] - mnew);
                s[i][j] = p; rs += p;
            }
#pragma unroll
            for (int off = 8; off >= 1; off >>= 1)
                rs += __shfl_xor_sync(0xffffffffu, rs, off);
            m_i[i] = mnew;
            l_i[i] = l_i[i] * corr + rs;
#pragma unroll
            for (int j = 0; j < 4; j++) {
                o[i][j] *= corr;
                Ps[(ty * 4 + i) * 65 + tx * 4 + j] = s[i][j];
            }
        }
        __syncthreads();

#pragma unroll 16
        for (int c = 0; c < 64; c++) {
            float pa[4], vb[4];
#pragma unroll
            for (int i = 0; i < 4; i++) pa[i] = Ps[(ty * 4 + i) * 65 + c];
#pragma unroll
            for (int j = 0; j < 4; j++) vb[j] = Vs[c * 65 + tx * 4 + j];
#pragma unroll
            for (int i = 0; i < 4; i++)
#pragma unroll
                for (int j = 0; j < 4; j++)
                    o[i][j] = fmaf(pa[i], vb[j], o[i][j]);
        }
    }

    const int b = bh / NH;
    const int h = bh - b * NH;
#pragma unroll
    for (int i = 0; i < 4; i++) {
        float inv = 1.0f / l_i[i];
        int srow = qt * 64 + ty * 4 + i;
        float* dst = g_attn + ((size_t)(b * SEQ + srow)) * ED + h * HD + tx * 4;
#pragma unroll
        for (int j = 0; j < 4; j++) dst[j] = o[i][j] * inv;
    }
}

// ---------------------------------------------------------------------------
// Launch
// ---------------------------------------------------------------------------
extern "C" void kernel_launch(void* const* d_in, const int* in_sizes, int n_in,
                              void* d_out, int out_size) {
    const float* x      = (const float*)d_in[0];
    const float* qkv_w  = (const float*)d_in[1];
    const float* qkv_b  = (const float*)d_in[2];
    const float* proj_w = (const float*)d_in[3];
    const float* proj_b = (const float*)d_in[4];
    float* out = (float*)d_out;

    cudaFuncSetAttribute(attn_kernel, cudaFuncAttributeMaxDynamicSharedMemorySize,
                         ATTN_SMEM_BYTES);
    cudaFuncSetAttribute(gemm_wmma<0>, cudaFuncAttributeMaxDynamicSharedMemorySize,
                         GEMM_SMEM_BYTES);
    cudaFuncSetAttribute(gemm_wmma<1>, cudaFuncAttributeMaxDynamicSharedMemorySize,
                         GEMM_SMEM_BYTES);

    // 1. QKV GEMM (fp32 in, inline bf16 split) -> g_q/g_k/g_v
    gemm_wmma<0><<<dim3(3 * ED / 128, MTOT / 128), 256, GEMM_SMEM_BYTES>>>(
        x, qkv_w, qkv_b, nullptr, 3 * ED);

    // 2. attention (R1-validated fp32) -> g_attn
    attn_kernel<<<dim3(SEQ / 64, NBATCH * NH), 256, ATTN_SMEM_BYTES>>>();

    // 3. projection -> out
    gemm_wmma<1><<<dim3(ED / 128, MTOT / 128), 256, GEMM_SMEM_BYTES>>>(
        nullptr, proj_w, proj_b, out, ED);
}